// round 1
// baseline (speedup 1.0000x reference)
#include <cuda_runtime.h>

#define NN    50000
#define EE    640000
#define DINN  128
#define DH    256
#define DOUTK 128

// ---------------- scratch (static device globals; no runtime allocation) ----
__device__ int   g_deg[NN];
__device__ float g_invc[NN];
__device__ int   g_rowstart[NN + 1];
__device__ int   g_cursor[NN];
__device__ int   g_csr[EE];
__device__ float g_agg[(size_t)NN * DH];
__device__ float g_T  [(size_t)NN * DH];
__device__ float g_S  [(size_t)NN * DH];
__device__ float g_H  [(size_t)NN * DH];
__device__ float g_H2 [(size_t)NN * DH];
__device__ float g_Y  [(size_t)NN * DOUTK];
__device__ float g_Z  [(size_t)NN * DOUTK];

// buffer ids: 0=g_agg 1=g_T 2=g_S 3=g_H 4=g_H2 5=g_Y 6=g_Z
__device__ __forceinline__ const float* resolve_c(const float* p, int id) {
  if (p) return p;
  switch (id) {
    case 0: return g_agg;
    case 1: return g_T;
    case 2: return g_S;
    case 3: return g_H;
    case 4: return g_H2;
    case 5: return g_Y;
    default: return g_Z;
  }
}
__device__ __forceinline__ float* resolve_m(int id) {
  switch (id) {
    case 0: return g_agg;
    case 1: return g_T;
    case 2: return g_S;
    case 3: return g_H;
    case 4: return g_H2;
    case 5: return g_Y;
    default: return g_Z;
  }
}

// ---------------- CSR build ------------------------------------------------
__global__ void zero_deg_kernel() {
  int i = blockIdx.x * blockDim.x + threadIdx.x;
  if (i < NN) g_deg[i] = 0;
}

__global__ void count_kernel(const int* __restrict__ dst) {
  int e = blockIdx.x * blockDim.x + threadIdx.x;
  if (e < EE) atomicAdd(&g_deg[dst[e]], 1);
}

__global__ void scan_kernel() {
  constexpr int T = 1024;
  constexpr int CHUNK = (NN + T - 1) / T;
  __shared__ int sums[T];
  const int tid = threadIdx.x;
  const int start = tid * CHUNK;
  const int end = (start + CHUNK < NN) ? (start + CHUNK) : NN;
  int s = 0;
  for (int i = start; i < end; ++i) s += g_deg[i];
  sums[tid] = s;
  __syncthreads();
  for (int off = 1; off < T; off <<= 1) {
    int v = 0;
    if (tid >= off) v = sums[tid - off];
    __syncthreads();
    if (tid >= off) sums[tid] += v;
    __syncthreads();
  }
  int run = (tid == 0) ? 0 : sums[tid - 1];
  for (int i = start; i < end; ++i) {
    const int d = g_deg[i];
    g_rowstart[i] = run;
    g_cursor[i]   = run;
    g_invc[i]     = 1.0f / (float)(d > 1 ? d : 1);
    run += d;
  }
  if (end == NN) g_rowstart[NN] = run;
}

__global__ void fill_kernel(const int* __restrict__ src, const int* __restrict__ dst) {
  int e = blockIdx.x * blockDim.x + threadIdx.x;
  if (e < EE) {
    int pos = atomicAdd(&g_cursor[dst[e]], 1);
    g_csr[pos] = src[e];
  }
}

// ---------------- mean aggregation (one warp per destination node) ---------
template <int D>
__global__ void agg_kernel(const float* Xp, int xid) {
  const float* __restrict__ X = resolve_c(Xp, xid);
  const int warp = (blockIdx.x * blockDim.x + threadIdx.x) >> 5;
  if (warp >= NN) return;
  const int lane = threadIdx.x & 31;
  constexpr int V = D / 128;  // float4 per lane
  float4 acc[V];
#pragma unroll
  for (int v = 0; v < V; ++v) acc[v] = make_float4(0.f, 0.f, 0.f, 0.f);
  const int beg = g_rowstart[warp];
  const int end = g_rowstart[warp + 1];
  for (int i = beg; i < end; ++i) {
    const int s = g_csr[i];
    const float4* row = (const float4*)(X + (size_t)s * D);
#pragma unroll
    for (int v = 0; v < V; ++v) {
      float4 t = row[lane + 32 * v];
      acc[v].x += t.x; acc[v].y += t.y; acc[v].z += t.z; acc[v].w += t.w;
    }
  }
  const float ic = g_invc[warp];
  float4* o = (float4*)(g_agg + (size_t)warp * D);
#pragma unroll
  for (int v = 0; v < V; ++v) {
    float4 r = acc[v];
    r.x *= ic; r.y *= ic; r.z *= ic; r.w *= ic;
    o[lane + 32 * v] = r;
  }
}

// final layer: out = mean_agg(Y) + Z + b3l   (aggregate AFTER projection)
__global__ void agg_final_kernel(const float* __restrict__ b3l, float* __restrict__ out) {
  const int warp = (blockIdx.x * blockDim.x + threadIdx.x) >> 5;
  if (warp >= NN) return;
  const int lane = threadIdx.x & 31;
  float4 acc = make_float4(0.f, 0.f, 0.f, 0.f);
  const int beg = g_rowstart[warp];
  const int end = g_rowstart[warp + 1];
  for (int i = beg; i < end; ++i) {
    const int s = g_csr[i];
    float4 t = *(const float4*)(g_Y + (size_t)s * DOUTK + lane * 4);
    acc.x += t.x; acc.y += t.y; acc.z += t.z; acc.w += t.w;
  }
  const float ic = g_invc[warp];
  float4 z = *(const float4*)(g_Z + (size_t)warp * DOUTK + lane * 4);
  float4 b = *(const float4*)(b3l + lane * 4);
  float4 r;
  r.x = acc.x * ic + z.x + b.x;
  r.y = acc.y * ic + z.y + b.y;
  r.z = acc.z * ic + z.z + b.z;
  r.w = acc.w * ic + z.w + b.w;
  *(float4*)(out + (size_t)warp * DOUTK + lane * 4) = r;
}

// ---------------- SGEMM: C = A1@B1 + A2@B2 (+bias), row-major ---------------
#define BM 128
#define BN 128
#define BKK 16
#define TM 8
#define TN 8

__global__ void __launch_bounds__(256, 2)
sgemm_kernel(const float* A1p, int a1id, const float* __restrict__ B1, int K1,
             const float* A2p, int a2id, const float* __restrict__ B2, int K2,
             const float* __restrict__ bias, int cid, int M) {
  __shared__ float As[BKK][BM + 4];
  __shared__ float Bs[BKK][BN];

  const int tid = threadIdx.x;
  const int rowTile = blockIdx.x * BM;
  const int colTile = blockIdx.y * BN;

  float acc[TM * TN];
#pragma unroll
  for (int i = 0; i < TM * TN; ++i) acc[i] = 0.f;

  const int tr = tid / (BN / TN);  // 0..15
  const int tc = tid % (BN / TN);  // 0..15
  const int aRow = tid >> 2;        // 0..63
  const int aCol = (tid & 3) * 4;   // 0,4,8,12
  const int bRow = tid >> 5;        // 0..7
  const int bCol = (tid & 31) * 4;  // 0..124

  for (int phase = 0; phase < 2; ++phase) {
    const int K = phase ? K2 : K1;
    if (K == 0) continue;
    const float* __restrict__ A = resolve_c(phase ? A2p : A1p, phase ? a2id : a1id);
    const float* __restrict__ B = phase ? B2 : B1;
    for (int k0 = 0; k0 < K; k0 += BKK) {
#pragma unroll
      for (int i = 0; i < 2; ++i) {
        const int r = aRow + i * 64;
        const int grow = rowTile + r;
        float4 v = make_float4(0.f, 0.f, 0.f, 0.f);
        if (grow < NN) v = *(const float4*)(A + (size_t)grow * K + k0 + aCol);
        As[aCol + 0][r] = v.x;
        As[aCol + 1][r] = v.y;
        As[aCol + 2][r] = v.z;
        As[aCol + 3][r] = v.w;
      }
#pragma unroll
      for (int i = 0; i < 2; ++i) {
        const int r = bRow + i * 8;
        *(float4*)&Bs[r][bCol] =
            *(const float4*)(B + (size_t)(k0 + r) * M + colTile + bCol);
      }
      __syncthreads();
#pragma unroll
      for (int k = 0; k < BKK; ++k) {
        float ra[TM], rb[TN];
        *(float4*)&ra[0] = *(const float4*)&As[k][tr * TM];
        *(float4*)&ra[4] = *(const float4*)&As[k][tr * TM + 4];
        *(float4*)&rb[0] = *(const float4*)&Bs[k][tc * TN];
        *(float4*)&rb[4] = *(const float4*)&Bs[k][tc * TN + 4];
#pragma unroll
        for (int i = 0; i < TM; ++i)
#pragma unroll
          for (int j = 0; j < TN; ++j)
            acc[i * TN + j] = fmaf(ra[i], rb[j], acc[i * TN + j]);
      }
      __syncthreads();
    }
  }

  float* __restrict__ C = resolve_m(cid);
#pragma unroll
  for (int i = 0; i < TM; ++i) {
    const int grow = rowTile + tr * TM + i;
    if (grow >= NN) break;
#pragma unroll
    for (int j = 0; j < TN; j += 4) {
      const int gcol = colTile + tc * TN + j;
      float4 v = make_float4(acc[i * TN + j], acc[i * TN + j + 1],
                             acc[i * TN + j + 2], acc[i * TN + j + 3]);
      if (bias) {
        float4 bv = *(const float4*)(bias + gcol);
        v.x += bv.x; v.y += bv.y; v.z += bv.z; v.w += bv.w;
      }
      *(float4*)(C + (size_t)grow * M + gcol) = v;
    }
  }
}

// ---------------- LayerNorm + ReLU + skip add (one warp per row, DH=256) ----
__global__ void ln_relu_add_kernel(const float* __restrict__ gamma,
                                   const float* __restrict__ beta,
                                   int sid, int outid) {
  const int row = (blockIdx.x * blockDim.x + threadIdx.x) >> 5;
  if (row >= NN) return;
  const int lane = threadIdx.x & 31;
  const float4* t4 = (const float4*)(g_T + (size_t)row * DH);
  float4 v0 = t4[lane];
  float4 v1 = t4[lane + 32];
  float sum = v0.x + v0.y + v0.z + v0.w + v1.x + v1.y + v1.z + v1.w;
  float sq = v0.x * v0.x + v0.y * v0.y + v0.z * v0.z + v0.w * v0.w +
             v1.x * v1.x + v1.y * v1.y + v1.z * v1.z + v1.w * v1.w;
#pragma unroll
  for (int off = 16; off > 0; off >>= 1) {
    sum += __shfl_xor_sync(0xffffffffu, sum, off);
    sq  += __shfl_xor_sync(0xffffffffu, sq, off);
  }
  const float mu = sum * (1.0f / DH);
  const float var = sq * (1.0f / DH) - mu * mu;
  const float rs = rsqrtf(var + 1e-5f);

  const float* __restrict__ S = resolve_c(nullptr, sid);
  float* __restrict__ O = resolve_m(outid);
  const float4* g4 = (const float4*)gamma;
  const float4* b4 = (const float4*)beta;
  const float4* s4 = (const float4*)(S + (size_t)row * DH);
  float4* o4 = (float4*)(O + (size_t)row * DH);

#pragma unroll
  for (int v = 0; v < 2; ++v) {
    float4 tv = (v == 0) ? v0 : v1;
    float4 gv = g4[lane + 32 * v];
    float4 bv = b4[lane + 32 * v];
    float4 sv = s4[lane + 32 * v];
    float4 r;
    r.x = fmaxf(0.f, (tv.x - mu) * rs * gv.x + bv.x) + sv.x;
    r.y = fmaxf(0.f, (tv.y - mu) * rs * gv.y + bv.y) + sv.y;
    r.z = fmaxf(0.f, (tv.z - mu) * rs * gv.z + bv.z) + sv.z;
    r.w = fmaxf(0.f, (tv.w - mu) * rs * gv.w + bv.w) + sv.w;
    o4[lane + 32 * v] = r;
  }
}

// ---------------- launch -----------------------------------------------------
extern "C" void kernel_launch(void* const* d_in, const int* in_sizes, int n_in,
                              void* d_out, int out_size) {
  const float* x   = (const float*)d_in[0];
  const int*   ei  = (const int*)d_in[1];
  const float* W1l = (const float*)d_in[2];
  const float* b1l = (const float*)d_in[3];
  const float* W1r = (const float*)d_in[4];
  const float* g1  = (const float*)d_in[5];
  const float* be1 = (const float*)d_in[6];
  const float* Wsk = (const float*)d_in[7];
  const float* bsk = (const float*)d_in[8];
  const float* W2l = (const float*)d_in[9];
  const float* b2l = (const float*)d_in[10];
  const float* W2r = (const float*)d_in[11];
  const float* g2  = (const float*)d_in[12];
  const float* be2 = (const float*)d_in[13];
  const float* W3l = (const float*)d_in[14];
  const float* b3l = (const float*)d_in[15];
  const float* W3r = (const float*)d_in[16];
  float* out = (float*)d_out;

  const int* src = ei;       // edge_index[0]
  const int* dst = ei + EE;  // edge_index[1]

  const int nodeBlocks = (NN + 255) / 256;         // 196
  const int edgeBlocks = (EE + 255) / 256;         // 2500
  const int warpBlocks = (NN + 7) / 8;             // 6250 (8 warps/block)
  const dim3 gemmGrid2((NN + BM - 1) / BM, 2);     // M=256
  const dim3 gemmGrid1((NN + BM - 1) / BM, 1);     // M=128

  // CSR build
  zero_deg_kernel<<<nodeBlocks, 256>>>();
  count_kernel<<<edgeBlocks, 256>>>(dst);
  scan_kernel<<<1, 1024>>>();
  fill_kernel<<<edgeBlocks, 256>>>(src, dst);

  // ---- layer 1: t = agg(x)@W1l + x@W1r + b1l ; s = x@Wsk + bsk ;
  //               h = relu(LN(t)) + s
  agg_kernel<128><<<warpBlocks, 256>>>(x, -1);
  sgemm_kernel<<<gemmGrid2, 256>>>(nullptr, 0, W1l, DINN, x, -1, W1r, DINN,
                                   b1l, 1, DH);
  sgemm_kernel<<<gemmGrid2, 256>>>(x, -1, Wsk, DINN, nullptr, 0, nullptr, 0,
                                   bsk, 2, DH);
  ln_relu_add_kernel<<<warpBlocks, 256>>>(g1, be1, 2, 3);

  // ---- layer 2: t = agg(h)@W2l + h@W2r + b2l ; h2 = relu(LN(t)) + h
  agg_kernel<256><<<warpBlocks, 256>>>(nullptr, 3);
  sgemm_kernel<<<gemmGrid2, 256>>>(nullptr, 0, W2l, DH, nullptr, 3, W2r, DH,
                                   b2l, 1, DH);
  ln_relu_add_kernel<<<warpBlocks, 256>>>(g2, be2, 3, 4);

  // ---- layer 3 (linearity: agg(h2)@W3l == agg(h2@W3l)):
  //      Y = h2@W3l ; Z = h2@W3r ; out = mean_agg(Y) + Z + b3l
  sgemm_kernel<<<gemmGrid1, 256>>>(nullptr, 4, W3l, DH, nullptr, 0, nullptr, 0,
                                   nullptr, 5, DOUTK);
  sgemm_kernel<<<gemmGrid1, 256>>>(nullptr, 4, W3r, DH, nullptr, 0, nullptr, 0,
                                   nullptr, 6, DOUTK);
  agg_final_kernel<<<warpBlocks, 256>>>(b3l, out);
}

// round 3
// speedup vs baseline: 1.3228x; 1.3228x over previous
#include <cuda_runtime.h>
#include <cuda_bf16.h>
#include <cstdint>

#define NN    50000
#define EE    640000
#define DINN  128
#define DH    256
#define DOUTK 128

// ===================== scratch =============================================
__device__ int   g_deg[NN];
__device__ float g_invc[NN];
__device__ int   g_rowstart[NN + 1];
__device__ int   g_cursor[NN];
__device__ int   g_csr[EE];
__device__ __align__(256) float g_agg[(size_t)NN * DH];
__device__ __align__(256) float g_T  [(size_t)NN * DH];
__device__ __align__(256) float g_S  [(size_t)NN * DH];
__device__ __align__(256) float g_H  [(size_t)NN * DH];
__device__ __align__(256) float g_H2 [(size_t)NN * DH];

// weights transposed+split into bf16 hi/lo, [N rows][K cols]
__device__ __align__(16) __nv_bfloat16 gB1h[256 * 256], gB1l[256 * 256];
__device__ __align__(16) __nv_bfloat16 gBskh[256 * 128], gBskl[256 * 128];
__device__ __align__(16) __nv_bfloat16 gB2h[256 * 512], gB2l[256 * 512];
__device__ __align__(16) __nv_bfloat16 gB3h[256 * 256], gB3l[256 * 256];

// buffer ids: 0=g_agg 1=g_T 2=g_S 3=g_H 4=g_H2
__device__ __forceinline__ const float* resolve_c(const float* p, int id) {
  if (p) return p;
  switch (id) {
    case 0: return g_agg;
    case 1: return g_T;
    case 2: return g_S;
    case 3: return g_H;
    default: return g_H2;
  }
}
__device__ __forceinline__ float* resolve_m(int id) {
  switch (id) {
    case 1: return g_T;
    default: return g_S;
  }
}
__device__ __forceinline__ void resolve_b(int id, const __nv_bfloat16** h,
                                          const __nv_bfloat16** l) {
  switch (id) {
    case 1: *h = gB1h;  *l = gB1l;  break;
    case 2: *h = gBskh; *l = gBskl; break;
    case 3: *h = gB2h;  *l = gB2l;  break;
    default:*h = gB3h;  *l = gB3l;  break;
  }
}
__device__ __forceinline__ void resolve_b_mut(int id, __nv_bfloat16** h,
                                              __nv_bfloat16** l) {
  switch (id) {
    case 1: *h = gB1h;  *l = gB1l;  break;
    case 2: *h = gBskh; *l = gBskl; break;
    case 3: *h = gB2h;  *l = gB2l;  break;
    default:*h = gB3h;  *l = gB3l;  break;
  }
}

// ===================== CSR build ===========================================
__global__ void zero_deg_kernel() {
  int i = blockIdx.x * blockDim.x + threadIdx.x;
  if (i < NN) g_deg[i] = 0;
}
__global__ void count_kernel(const int* __restrict__ dst) {
  int e = blockIdx.x * blockDim.x + threadIdx.x;
  if (e < EE) atomicAdd(&g_deg[dst[e]], 1);
}
__global__ void scan_kernel() {
  constexpr int T = 1024;
  constexpr int CHUNK = (NN + T - 1) / T;
  __shared__ int sums[T];
  const int tid = threadIdx.x;
  const int start = tid * CHUNK;
  const int end = (start + CHUNK < NN) ? (start + CHUNK) : NN;
  int s = 0;
  for (int i = start; i < end; ++i) s += g_deg[i];
  sums[tid] = s;
  __syncthreads();
  for (int off = 1; off < T; off <<= 1) {
    int v = 0;
    if (tid >= off) v = sums[tid - off];
    __syncthreads();
    if (tid >= off) sums[tid] += v;
    __syncthreads();
  }
  int run = (tid == 0) ? 0 : sums[tid - 1];
  for (int i = start; i < end; ++i) {
    const int d = g_deg[i];
    g_rowstart[i] = run;
    g_cursor[i]   = run;
    g_invc[i]     = 1.0f / (float)(d > 1 ? d : 1);
    run += d;
  }
  if (end == NN) g_rowstart[NN] = run;
}
__global__ void fill_kernel(const int* __restrict__ src, const int* __restrict__ dst) {
  int e = blockIdx.x * blockDim.x + threadIdx.x;
  if (e < EE) {
    int pos = atomicAdd(&g_cursor[dst[e]], 1);
    g_csr[pos] = src[e];
  }
}

// ===================== mean aggregation ====================================
template <int D>
__global__ void agg_kernel(const float* Xp, int xid) {
  const float* __restrict__ X = resolve_c(Xp, xid);
  const int warp = (blockIdx.x * blockDim.x + threadIdx.x) >> 5;
  if (warp >= NN) return;
  const int lane = threadIdx.x & 31;
  constexpr int V = D / 128;
  float4 acc[V];
#pragma unroll
  for (int v = 0; v < V; ++v) acc[v] = make_float4(0.f, 0.f, 0.f, 0.f);
  const int beg = g_rowstart[warp];
  const int end = g_rowstart[warp + 1];
  for (int i = beg; i < end; ++i) {
    const int s = g_csr[i];
    const float4* row = (const float4*)(X + (size_t)s * D);
#pragma unroll
    for (int v = 0; v < V; ++v) {
      float4 t = row[lane + 32 * v];
      acc[v].x += t.x; acc[v].y += t.y; acc[v].z += t.z; acc[v].w += t.w;
    }
  }
  const float ic = g_invc[warp];
  float4* o = (float4*)(g_agg + (size_t)warp * D);
#pragma unroll
  for (int v = 0; v < V; ++v) {
    float4 r = acc[v];
    r.x *= ic; r.y *= ic; r.z *= ic; r.w *= ic;
    o[lane + 32 * v] = r;
  }
}

// final layer: out = mean_agg(Y) + Z + b3l ; Y = g_T cols[0:128), Z = cols[128:256)
__global__ void agg_final_kernel(const float* __restrict__ b3l, float* __restrict__ out) {
  const int warp = (blockIdx.x * blockDim.x + threadIdx.x) >> 5;
  if (warp >= NN) return;
  const int lane = threadIdx.x & 31;
  float4 acc = make_float4(0.f, 0.f, 0.f, 0.f);
  const int beg = g_rowstart[warp];
  const int end = g_rowstart[warp + 1];
  for (int i = beg; i < end; ++i) {
    const int s = g_csr[i];
    float4 t = *(const float4*)(g_T + (size_t)s * DH + lane * 4);
    acc.x += t.x; acc.y += t.y; acc.z += t.z; acc.w += t.w;
  }
  const float ic = g_invc[warp];
  float4 z = *(const float4*)(g_T + (size_t)warp * DH + 128 + lane * 4);
  float4 b = *(const float4*)(b3l + lane * 4);
  float4 r;
  r.x = acc.x * ic + z.x + b.x;
  r.y = acc.y * ic + z.y + b.y;
  r.z = acc.z * ic + z.z + b.z;
  r.w = acc.w * ic + z.w + b.w;
  *(float4*)(out + (size_t)warp * DOUTK + lane * 4) = r;
}

// ===================== weight prep: transpose + bf16 hi/lo =================
__global__ void prep_w(const float* __restrict__ W, int K, int N, int bid,
                       int outStride, int kOff, int nOff) {
  int idx = blockIdx.x * blockDim.x + threadIdx.x;
  if (idx >= K * N) return;
  int k = idx / N, n = idx % N;
  float f = W[idx];
  __nv_bfloat16 h = __float2bfloat16(f);
  __nv_bfloat16 l = __float2bfloat16(f - __bfloat162float(h));
  __nv_bfloat16 *H, *L;
  resolve_b_mut(bid, &H, &L);
  size_t o = (size_t)(nOff + n) * outStride + kOff + k;
  H[o] = h;
  L[o] = l;
}

// ===================== bf16 MMA GEMM (mma.sync, compensated) ===============
// C[M=50000, 256] = A @ B^T (+bias). A fp32 split in-flight into bf16 hi/lo.
// B pre-split bf16 [n][K]. Fragment-order SMEM staging: no ldmatrix needed.
// CTA tile 128x128, K-chunk 16, double-buffered, 8 warps (4 M x 2 N).

__device__ __forceinline__ void mma_bf16(float* d, const uint32_t* a,
                                         const uint32_t* b) {
  asm volatile(
      "mma.sync.aligned.m16n8k16.row.col.f32.bf16.bf16.f32 "
      "{%0,%1,%2,%3}, {%4,%5,%6,%7}, {%8,%9}, {%0,%1,%2,%3};"
      : "+f"(d[0]), "+f"(d[1]), "+f"(d[2]), "+f"(d[3])
      : "r"(a[0]), "r"(a[1]), "r"(a[2]), "r"(a[3]), "r"(b[0]), "r"(b[1]));
}

__global__ void __launch_bounds__(256, 1)
gemm_mma(const float* A1p, int a1id, int K1,
         const float* A2p, int a2id, int K2,
         int bId, int Kstride, const float* bias, int cid) {
  // stage layout (b32 units): A_hi[0,1024) A_lo[1024,2048) B_hi[2048,3072) B_lo[3072,4096)
  __shared__ uint32_t smem[2][4096];

  const int tid = threadIdx.x;
  const int wid = tid >> 5;
  const int lane = tid & 31;
  const int rowTile = blockIdx.x * 128;
  const int colTile = blockIdx.y * 128;

  const __nv_bfloat16 *Bh, *Bl;
  resolve_b(bId, &Bh, &Bl);

  // ---- precompute fragment-order staging addresses ----
  int aM[4], aP[4], addrA[4];
#pragma unroll
  for (int i = 0; i < 4; ++i) {
    const int idx = i * 256 + tid;       // 1024 float2 slots: A 128m x 8 kpairs
    const int m = idx >> 3, p = idx & 7;
    aM[i] = m; aP[i] = p;
    const int mtile = m >> 4, row_in = m & 15;
    const int l = ((row_in & 7) << 2) | (p & 3);
    const int reg = ((row_in >> 3) & 1) | ((p >> 2) << 1);
    addrA[i] = mtile * 128 + l * 4 + reg;
  }
  int bOff[8], addrB[8];
#pragma unroll
  for (int i = 0; i < 8; ++i) {
    const int idx = i * 256 + tid;       // 2048 b32 slots: 2 splits x 128n x 8 kpairs
    const int split = idx >> 10;
    const int rem = idx & 1023;
    const int n = rem >> 3, p = rem & 7;
    const int ntile = n >> 3, n_in = n & 7;
    const int l = (n_in << 2) | (p & 3);
    const int reg = p >> 2;
    addrB[i] = 2048 + split * 1024 + ntile * 64 + l * 2 + reg;
    bOff[i] = (colTile + n) * Kstride + 2 * p;
  }

  const int nChunks = (K1 + K2) >> 4;

  float2 aV[4];
  uint32_t bV[8];

  auto ldgChunk = [&](int c) {
    const int k0 = c * 16;
    const float* As; int aoff, astr;
    if (k0 < K1) { As = resolve_c(A1p, a1id); aoff = k0;      astr = K1; }
    else         { As = resolve_c(A2p, a2id); aoff = k0 - K1; astr = K2; }
#pragma unroll
    for (int i = 0; i < 4; ++i) {
      const int grow = rowTile + aM[i];
      float2 v = make_float2(0.f, 0.f);
      if (grow < NN) v = *(const float2*)(As + (size_t)grow * astr + aoff + 2 * aP[i]);
      aV[i] = v;
    }
#pragma unroll
    for (int i = 0; i < 8; ++i) {
      const __nv_bfloat16* Bp = (i < 4) ? Bh : Bl;
      bV[i] = *(const uint32_t*)(Bp + bOff[i] + k0);
    }
  };
  auto stsChunk = [&](int buf) {
    uint32_t* st = smem[buf];
#pragma unroll
    for (int i = 0; i < 4; ++i) {
      const __nv_bfloat16 hx = __float2bfloat16(aV[i].x);
      const __nv_bfloat16 hy = __float2bfloat16(aV[i].y);
      const __nv_bfloat16 lx = __float2bfloat16(aV[i].x - __bfloat162float(hx));
      const __nv_bfloat16 ly = __float2bfloat16(aV[i].y - __bfloat162float(hy));
      const uint32_t hp = ((uint32_t)__bfloat16_as_ushort(hy) << 16) | __bfloat16_as_ushort(hx);
      const uint32_t lp = ((uint32_t)__bfloat16_as_ushort(ly) << 16) | __bfloat16_as_ushort(lx);
      st[addrA[i]] = hp;
      st[1024 + addrA[i]] = lp;
    }
#pragma unroll
    for (int i = 0; i < 8; ++i) st[addrB[i]] = bV[i];
  };

  float acc[2][8][4];
#pragma unroll
  for (int mt = 0; mt < 2; ++mt)
#pragma unroll
    for (int nt = 0; nt < 8; ++nt)
#pragma unroll
      for (int r = 0; r < 4; ++r) acc[mt][nt][r] = 0.f;

  const int warpM = wid >> 1;  // 0..3
  const int warpN = wid & 1;   // 0..1

  ldgChunk(0);
  stsChunk(0);
  __syncthreads();

  for (int c = 0; c < nChunks; ++c) {
    const int buf = c & 1;
    if (c + 1 < nChunks) ldgChunk(c + 1);

    const uint32_t* st = smem[buf];
    uint4 ah[2], al[2];
    uint2 bh[8], bl[8];
#pragma unroll
    for (int mt = 0; mt < 2; ++mt) {
      const int mg = warpM * 2 + mt;
      ah[mt] = *(const uint4*)&st[mg * 128 + lane * 4];
      al[mt] = *(const uint4*)&st[1024 + mg * 128 + lane * 4];
    }
#pragma unroll
    for (int nt = 0; nt < 8; ++nt) {
      const int ng = warpN * 8 + nt;
      bh[nt] = *(const uint2*)&st[2048 + ng * 64 + lane * 2];
      bl[nt] = *(const uint2*)&st[3072 + ng * 64 + lane * 2];
    }
    // pass-major ordering: 16 independent accumulators between reuses
#pragma unroll
    for (int mt = 0; mt < 2; ++mt)
#pragma unroll
      for (int nt = 0; nt < 8; ++nt)
        mma_bf16(acc[mt][nt], (const uint32_t*)&ah[mt], (const uint32_t*)&bh[nt]);
#pragma unroll
    for (int mt = 0; mt < 2; ++mt)
#pragma unroll
      for (int nt = 0; nt < 8; ++nt)
        mma_bf16(acc[mt][nt], (const uint32_t*)&ah[mt], (const uint32_t*)&bl[nt]);
#pragma unroll
    for (int mt = 0; mt < 2; ++mt)
#pragma unroll
      for (int nt = 0; nt < 8; ++nt)
        mma_bf16(acc[mt][nt], (const uint32_t*)&al[mt], (const uint32_t*)&bh[nt]);

    if (c + 1 < nChunks) stsChunk((c + 1) & 1);
    __syncthreads();
  }

  // ---- epilogue ----
  float* __restrict__ C = resolve_m(cid);
  const int r0base = rowTile + warpM * 32 + (lane >> 2);
  const int cbase = colTile + warpN * 64 + (lane & 3) * 2;
#pragma unroll
  for (int mt = 0; mt < 2; ++mt) {
    const int r0 = r0base + mt * 16;
#pragma unroll
    for (int nt = 0; nt < 8; ++nt) {
      const int col = cbase + nt * 8;
      float2 bv = make_float2(0.f, 0.f);
      if (bias) bv = *(const float2*)(bias + col);
      if (r0 < NN) {
        float2 v = make_float2(acc[mt][nt][0] + bv.x, acc[mt][nt][1] + bv.y);
        *(float2*)(C + (size_t)r0 * 256 + col) = v;
      }
      if (r0 + 8 < NN) {
        float2 v = make_float2(acc[mt][nt][2] + bv.x, acc[mt][nt][3] + bv.y);
        *(float2*)(C + (size_t)(r0 + 8) * 256 + col) = v;
      }
    }
  }
}

// ===================== LayerNorm + ReLU + skip =============================
__global__ void ln_relu_add_kernel(const float* __restrict__ gamma,
                                   const float* __restrict__ beta,
                                   int sid, int outid) {
  const int row = (blockIdx.x * blockDim.x + threadIdx.x) >> 5;
  if (row >= NN) return;
  const int lane = threadIdx.x & 31;
  const float4* t4 = (const float4*)(g_T + (size_t)row * DH);
  float4 v0 = t4[lane];
  float4 v1 = t4[lane + 32];
  float sum = v0.x + v0.y + v0.z + v0.w + v1.x + v1.y + v1.z + v1.w;
  float sq = v0.x * v0.x + v0.y * v0.y + v0.z * v0.z + v0.w * v0.w +
             v1.x * v1.x + v1.y * v1.y + v1.z * v1.z + v1.w * v1.w;
#pragma unroll
  for (int off = 16; off > 0; off >>= 1) {
    sum += __shfl_xor_sync(0xffffffffu, sum, off);
    sq  += __shfl_xor_sync(0xffffffffu, sq, off);
  }
  const float mu = sum * (1.0f / DH);
  const float var = sq * (1.0f / DH) - mu * mu;
  const float rs = rsqrtf(var + 1e-5f);

  const float* __restrict__ S = (sid == 2) ? g_S : g_H;
  float* __restrict__ O = (outid == 3) ? g_H : g_H2;
  const float4* g4 = (const float4*)gamma;
  const float4* b4 = (const float4*)beta;
  const float4* s4 = (const float4*)(S + (size_t)row * DH);
  float4* o4 = (float4*)(O + (size_t)row * DH);
#pragma unroll
  for (int v = 0; v < 2; ++v) {
    float4 tv = (v == 0) ? v0 : v1;
    float4 gv = g4[lane + 32 * v];
    float4 bv = b4[lane + 32 * v];
    float4 sv = s4[lane + 32 * v];
    float4 r;
    r.x = fmaxf(0.f, (tv.x - mu) * rs * gv.x + bv.x) + sv.x;
    r.y = fmaxf(0.f, (tv.y - mu) * rs * gv.y + bv.y) + sv.y;
    r.z = fmaxf(0.f, (tv.z - mu) * rs * gv.z + bv.z) + sv.z;
    r.w = fmaxf(0.f, (tv.w - mu) * rs * gv.w + bv.w) + sv.w;
    o4[lane + 32 * v] = r;
  }
}

// ===================== launch ==============================================
extern "C" void kernel_launch(void* const* d_in, const int* in_sizes, int n_in,
                              void* d_out, int out_size) {
  const float* x   = (const float*)d_in[0];
  const int*   ei  = (const int*)d_in[1];
  const float* W1l = (const float*)d_in[2];
  const float* b1l = (const float*)d_in[3];
  const float* W1r = (const float*)d_in[4];
  const float* g1  = (const float*)d_in[5];
  const float* be1 = (const float*)d_in[6];
  const float* Wsk = (const float*)d_in[7];
  const float* bsk = (const float*)d_in[8];
  const float* W2l = (const float*)d_in[9];
  const float* b2l = (const float*)d_in[10];
  const float* W2r = (const float*)d_in[11];
  const float* g2  = (const float*)d_in[12];
  const float* be2 = (const float*)d_in[13];
  const float* W3l = (const float*)d_in[14];
  const float* b3l = (const float*)d_in[15];
  const float* W3r = (const float*)d_in[16];
  float* out = (float*)d_out;

  const int* src = ei;
  const int* dst = ei + EE;

  const int nodeBlocks = (NN + 255) / 256;
  const int edgeBlocks = (EE + 255) / 256;
  const int warpBlocks = (NN + 7) / 8;
  const dim3 gemmGrid((NN + 127) / 128, 2);

  // CSR build
  zero_deg_kernel<<<nodeBlocks, 256>>>();
  count_kernel<<<edgeBlocks, 256>>>(dst);
  scan_kernel<<<1, 1024>>>();
  fill_kernel<<<edgeBlocks, 256>>>(src, dst);

  // weight prep (transpose + bf16 hi/lo split)
  prep_w<<<(128 * 256 + 255) / 256, 256>>>(W1l, 128, 256, 1, 256, 0, 0);
  prep_w<<<(128 * 256 + 255) / 256, 256>>>(W1r, 128, 256, 1, 256, 128, 0);
  prep_w<<<(128 * 256 + 255) / 256, 256>>>(Wsk, 128, 256, 2, 128, 0, 0);
  prep_w<<<(256 * 256 + 255) / 256, 256>>>(W2l, 256, 256, 3, 512, 0, 0);
  prep_w<<<(256 * 256 + 255) / 256, 256>>>(W2r, 256, 256, 3, 512, 256, 0);
  prep_w<<<(256 * 128 + 255) / 256, 256>>>(W3l, 256, 128, 4, 256, 0, 0);
  prep_w<<<(256 * 128 + 255) / 256, 256>>>(W3r, 256, 128, 4, 256, 0, 128);

  // ---- layer 1: T = agg(x)@W1l + x@W1r + b1l ; S = x@Wsk + bsk ;
  //               H = relu(LN(T)) + S
  agg_kernel<128><<<warpBlocks, 256>>>(x, -1);
  gemm_mma<<<gemmGrid, 256>>>(nullptr, 0, 128, x, -1, 128, 1, 256, b1l, 1);
  gemm_mma<<<gemmGrid, 256>>>(x, -1, 128, nullptr, 0, 0, 2, 128, bsk, 2);
  ln_relu_add_kernel<<<warpBlocks, 256>>>(g1, be1, 2, 3);

  // ---- layer 2: T = agg(H)@W2l + H@W2r + b2l ; H2 = relu(LN(T)) + H
  agg_kernel<256><<<warpBlocks, 256>>>(nullptr, 3);
  gemm_mma<<<gemmGrid, 256>>>(nullptr, 0, 256, nullptr, 3, 256, 3, 512, b2l, 1);
  ln_relu_add_kernel<<<warpBlocks, 256>>>(g2, be2, 3, 4);

  // ---- layer 3 (agg after projection; Y|Z fused into one N=256 GEMM):
  //      T[:,0:128] = H2@W3l ; T[:,128:256] = H2@W3r ;
  //      out = mean_agg(T[:,0:128]) + T[:,128:256] + b3l
  gemm_mma<<<gemmGrid, 256>>>(nullptr, 4, 256, nullptr, 0, 0, 4, 256, nullptr, 1);
  agg_final_kernel<<<warpBlocks, 256>>>(b3l, out);
}